// round 1
// baseline (speedup 1.0000x reference)
#include <cuda_runtime.h>
#include <math.h>

// Shapes (fixed for this problem)
#define NB    2
#define NN    256
#define NK    16
#define ND    64
#define NHID  128
#define NKVD  256
#define NODES 512           // b*n
#define EDGES 8192          // b*n*k
#define KAUG  4160          // 64*64 outer-product K + 64 bias rows

// ---------------- scratch (device globals; no allocation) ----------------
__device__ float g_x[NODES*ND];
__device__ float g_q[NODES*NHID];
__device__ float g_xi[NODES*ND];
__device__ float g_xj[NODES*ND];
__device__ float g_hdd[EDGES*64];
__device__ float g_xe[EDGES*ND];
__device__ float g_wcomb[KAUG*NKVD];
__device__ float g_kv[EDGES*NKVD];
__device__ float g_maskf[EDGES];

// 64-thread block sum (2 warps)
__device__ __forceinline__ float blocksum64(float v, volatile float* sbuf, int t){
  #pragma unroll
  for (int o = 16; o; o >>= 1) v += __shfl_xor_sync(0xffffffffu, v, o);
  __syncthreads();
  if ((t & 31) == 0) sbuf[t >> 5] = v;
  __syncthreads();
  return sbuf[0] + sbuf[1];
}

__device__ __forceinline__ float silu(float x){ return x / (1.f + expf(-x)); }

// ---------------- mask dtype detection + expansion ----------------
// neighbor_mask serialization is ambiguous (bool). Detect from byte patterns:
//   any byte == 0x3f            -> float32 (1.0f has 0x3f in byte 3)
//   nonzero byte at i%4 != 0    -> uint8/bool (1-byte elements)
//   else                        -> int32
__global__ void k_mask(const unsigned char* __restrict__ mraw){
  __shared__ int flags[2];
  int t = threadIdx.x;
  if (t < 2) flags[t] = 0;
  __syncthreads();
  int f3 = 0, fn = 0;
  for (int i = t; i < EDGES; i += 256){        // first 8192 bytes: safe in all cases
    unsigned char bb = mraw[i];
    if (bb == 0x3fu) f3 = 1;
    if ((i & 3) && bb) fn = 1;
  }
  if (f3) atomicOr(&flags[0], 1);
  if (fn) atomicOr(&flags[1], 1);
  __syncthreads();
  int mode = flags[0] ? 2 : (flags[1] ? 0 : 1); // 2=f32, 0=u8, 1=i32
  for (int i = t; i < EDGES; i += 256){
    float m;
    if (mode == 2)      m = (((const float*)mraw)[i] != 0.f) ? 1.f : 0.f;
    else if (mode == 1) m = (((const int*)  mraw)[i] != 0  ) ? 1.f : 0.f;
    else                m = (mraw[i] != 0) ? 1.f : 0.f;
    g_maskf[i] = m;
  }
}

// ---------------- prenorm: per-node scalar RMS over d ----------------
__global__ void k_prenorm(const float* __restrict__ f, const float* __restrict__ nscale){
  __shared__ float sbuf[2];
  int node = blockIdx.x, t = threadIdx.x;
  float v  = f[node*ND + t];
  float ss = blocksum64(v*v, sbuf, t);
  float rms = sqrtf(ss) * 0.125f;              // * d^-0.5
  float den = fmaxf(rms, 1e-12f);
  g_x[node*ND + t] = v / den * nscale[t];
}

// ---------------- q / xi / xj projections ----------------
__global__ void k_proj(const float* __restrict__ Wq, const float* __restrict__ Wxi,
                       const float* __restrict__ Wxj){
  __shared__ float sx[ND];
  int node = blockIdx.x, t = threadIdx.x;
  if (t < ND) sx[t] = g_x[node*ND + t];
  __syncthreads();
  if (t < NHID){
    float a = 0.f;
    #pragma unroll
    for (int d = 0; d < ND; d++) a = fmaf(sx[d], Wq[d*NHID + t], a);
    g_q[node*NHID + t] = a;
  } else if (t < NHID + ND){
    int c = t - NHID; float a = 0.f;
    #pragma unroll
    for (int d = 0; d < ND; d++) a = fmaf(sx[d], Wxi[d*ND + c], a);
    g_xi[node*ND + c] = a;
  } else {
    int c = t - NHID - ND; float a = 0.f;
    #pragma unroll
    for (int d = 0; d < ND; d++) a = fmaf(sx[d], Wxj[d*ND + c], a);
    g_xj[node*ND + c] = a;
  }
}

// ---------------- radial MLP (per edge): 2x (linear -> silu -> LN) ----------------
__global__ void k_radial(const float* __restrict__ rel,
                         const float* __restrict__ W1, const float* __restrict__ b1,
                         const float* __restrict__ g1, const float* __restrict__ W2,
                         const float* __restrict__ b2, const float* __restrict__ g2){
  __shared__ float sh[64];
  __shared__ float sbuf[2];
  int e = blockIdx.x, t = threadIdx.x;
  float r = rel[e];
  float h = silu(fmaf(r, W1[t], b1[t]));
  float mu  = blocksum64(h, sbuf, t) * (1.f/64.f);
  float c   = h - mu;
  float var = blocksum64(c*c, sbuf, t) * (1.f/64.f);
  h = c * rsqrtf(var + 1e-5f) * g1[t];
  sh[t] = h;
  __syncthreads();
  float h2 = b2[t];
  #pragma unroll
  for (int i = 0; i < 64; i++) h2 = fmaf(sh[i], W2[i*64 + t], h2);
  h2 = silu(h2);
  float mu2  = blocksum64(h2, sbuf, t) * (1.f/64.f);
  float c2   = h2 - mu2;
  float var2 = blocksum64(c2*c2, sbuf, t) * (1.f/64.f);
  g_hdd[e*64 + t] = c2 * rsqrtf(var2 + 1e-5f) * g2[t];
}

// ---------------- W_comb[(r,d)||bias_d, o2] = (W3-gather || b3) @ Wkv_out ----------------
__global__ void k_wcomb(const float* __restrict__ W3, const float* __restrict__ b3,
                        const float* __restrict__ Wkv){
  __shared__ float w3s[16][256];
  int c0 = blockIdx.x * 16;
  int t  = threadIdx.x;                        // = o index on load, o2 index in loop
  #pragma unroll
  for (int cc = 0; cc < 16; cc++){
    int c = c0 + cc;
    float v;
    if (c < 4096){
      int r = c >> 6, d = c & 63;
      v = W3[r*16384 + t*64 + d];
    } else {
      int d = c - 4096;
      v = b3[t*64 + d];
    }
    w3s[cc][t] = v;
  }
  __syncthreads();
  float acc[16];
  #pragma unroll
  for (int cc = 0; cc < 16; cc++) acc[cc] = 0.f;
  for (int o = 0; o < 256; o++){
    float wv = Wkv[o*256 + t];
    #pragma unroll
    for (int cc = 0; cc < 16; cc++) acc[cc] = fmaf(w3s[cc][o], wv, acc[cc]);
  }
  #pragma unroll
  for (int cc = 0; cc < 16; cc++) g_wcomb[(c0 + cc)*256 + t] = acc[cc];
}

// ---------------- xe[e] = xj[neighbor] + xi[node] ----------------
__global__ void k_xe(const int* __restrict__ nidx){
  int e = blockIdx.x, t = threadIdx.x;
  int node = e >> 4;
  int b    = node >> 8;
  int nb   = b*NN + nidx[e];
  g_xe[e*ND + t] = g_xj[nb*ND + t] + g_xi[node*ND + t];
}

// ---------------- main GEMM: kv2[8192,256] = P_aug @ W_comb ----------------
// A built on the fly: A[e, r*64+kk] = hdd[e,r]*xe[e,kk]; bias tile A[e,kk]=xe[e,kk].
// Per r-tile: t_ij = sum_kk xe[m_i][kk]*W[kk][n_j]; acc += h[m_i]*t_ij.
__global__ void __launch_bounds__(256) k_gemm(){
  __shared__ float sxe[64][64];   // [e][d]
  __shared__ float shd[64][64];   // [e][r]
  __shared__ float sw [64][64];   // [k][n]
  int m0 = blockIdx.x * 64;
  int n0 = blockIdx.y * 64;
  int tid = threadIdx.x;
  int tx = tid & 15, ty = tid >> 4;

  #pragma unroll
  for (int i = 0; i < 16; i++){
    int idx = tid + i*256;
    int e = idx >> 6, dd = idx & 63;
    sxe[e][dd] = g_xe [(m0+e)*ND + dd];
    shd[e][dd] = g_hdd[(m0+e)*64 + dd];
  }
  __syncthreads();

  float acc[4][4];
  #pragma unroll
  for (int i=0;i<4;i++)
    #pragma unroll
    for (int j=0;j<4;j++) acc[i][j] = 0.f;

  for (int r = 0; r < 65; r++){                 // 64 outer-product tiles + 1 bias tile
    int rowbase = (r < 64) ? r*64 : 4096;
    #pragma unroll
    for (int i = 0; i < 16; i++){
      int idx = tid + i*256;
      int kk = idx >> 6, j = idx & 63;
      sw[kk][j] = g_wcomb[(rowbase + kk)*NKVD + n0 + j];
    }
    __syncthreads();

    float tt[4][4];
    #pragma unroll
    for (int i=0;i<4;i++)
      #pragma unroll
      for (int j=0;j<4;j++) tt[i][j] = 0.f;

    #pragma unroll
    for (int kk = 0; kk < 64; kk++){
      float4 bv = *(const float4*)&sw[kk][tx*4];
      float a0 = sxe[ty*4+0][kk];
      float a1 = sxe[ty*4+1][kk];
      float a2 = sxe[ty*4+2][kk];
      float a3 = sxe[ty*4+3][kk];
      tt[0][0]=fmaf(a0,bv.x,tt[0][0]); tt[0][1]=fmaf(a0,bv.y,tt[0][1]);
      tt[0][2]=fmaf(a0,bv.z,tt[0][2]); tt[0][3]=fmaf(a0,bv.w,tt[0][3]);
      tt[1][0]=fmaf(a1,bv.x,tt[1][0]); tt[1][1]=fmaf(a1,bv.y,tt[1][1]);
      tt[1][2]=fmaf(a1,bv.z,tt[1][2]); tt[1][3]=fmaf(a1,bv.w,tt[1][3]);
      tt[2][0]=fmaf(a2,bv.x,tt[2][0]); tt[2][1]=fmaf(a2,bv.y,tt[2][1]);
      tt[2][2]=fmaf(a2,bv.z,tt[2][2]); tt[2][3]=fmaf(a2,bv.w,tt[2][3]);
      tt[3][0]=fmaf(a3,bv.x,tt[3][0]); tt[3][1]=fmaf(a3,bv.y,tt[3][1]);
      tt[3][2]=fmaf(a3,bv.z,tt[3][2]); tt[3][3]=fmaf(a3,bv.w,tt[3][3]);
    }
    float h[4];
    if (r < 64){
      #pragma unroll
      for (int i=0;i<4;i++) h[i] = shd[ty*4+i][r];
    } else {
      #pragma unroll
      for (int i=0;i<4;i++) h[i] = 1.f;
    }
    #pragma unroll
    for (int i=0;i<4;i++)
      #pragma unroll
      for (int j=0;j<4;j++) acc[i][j] = fmaf(h[i], tt[i][j], acc[i][j]);
    __syncthreads();
  }

  #pragma unroll
  for (int i=0;i<4;i++)
    #pragma unroll
    for (int j=0;j<4;j++)
      g_kv[(m0 + ty*4 + i)*NKVD + n0 + tx*4 + j] = acc[i][j];
}

// ---------------- L2-distance attention + output projection ----------------
__global__ void k_attn(const float* __restrict__ Wout, float* __restrict__ out){
  __shared__ float s_out[NHID];
  int node = blockIdx.x;
  int tid  = threadIdx.x;
  int warp = tid >> 5;       // = head
  float qv = g_q[node*NHID + tid];

  float sim[NK];
  #pragma unroll
  for (int j = 0; j < NK; j++){
    int e = node*NK + j;
    float kvv = g_kv[e*NKVD + tid];           // kk half: cols [0,128)
    float dff = qv - kvv + 1e-6f;
    float s = dff * dff;
    #pragma unroll
    for (int o = 16; o; o >>= 1) s += __shfl_xor_sync(0xffffffffu, s, o);
    float m = g_maskf[e];
    sim[j] = (m != 0.f) ? (-sqrtf(s) * 0.17677669529663687f) : -3.402823466e38f;
  }
  float mx = sim[0];
  #pragma unroll
  for (int j = 1; j < NK; j++) mx = fmaxf(mx, sim[j]);
  float p[NK], den = 0.f;
  #pragma unroll
  for (int j = 0; j < NK; j++){ p[j] = expf(sim[j] - mx); den += p[j]; }
  float o = 0.f;
  #pragma unroll
  for (int j = 0; j < NK; j++){
    int e = node*NK + j;
    o = fmaf(p[j], g_kv[e*NKVD + NHID + tid], o);   // vv half
  }
  s_out[tid] = o / den;
  __syncthreads();
  (void)warp;
  if (tid < ND){
    float a = 0.f;
    #pragma unroll
    for (int c = 0; c < NHID; c++) a = fmaf(s_out[c], Wout[c*ND + tid], a);
    out[node*ND + tid] = a;
  }
}

// ---------------- launch ----------------
extern "C" void kernel_launch(void* const* d_in, const int* in_sizes, int n_in,
                              void* d_out, int out_size){
  const float* features = (const float*)d_in[0];
  const int*   nidx     = (const int*)  d_in[1];
  const unsigned char* mask = (const unsigned char*)d_in[2];
  const float* rel      = (const float*)d_in[3];
  const float* nscale   = (const float*)d_in[4];
  const float* Wq       = (const float*)d_in[5];
  const float* Wxi      = (const float*)d_in[6];
  const float* Wxj      = (const float*)d_in[7];
  const float* rp_W1    = (const float*)d_in[8];
  const float* rp_b1    = (const float*)d_in[9];
  const float* rp_g1    = (const float*)d_in[10];
  const float* rp_W2    = (const float*)d_in[11];
  const float* rp_b2    = (const float*)d_in[12];
  const float* rp_g2    = (const float*)d_in[13];
  const float* rp_W3    = (const float*)d_in[14];
  const float* rp_b3    = (const float*)d_in[15];
  const float* Wkv      = (const float*)d_in[16];
  const float* Wout     = (const float*)d_in[17];
  float* out = (float*)d_out;

  k_mask   <<<1, 256>>>(mask);
  k_prenorm<<<NODES, 64>>>(features, nscale);
  k_proj   <<<NODES, 256>>>(Wq, Wxi, Wxj);
  k_radial <<<EDGES, 64>>>(rel, rp_W1, rp_b1, rp_g1, rp_W2, rp_b2, rp_g2);
  k_wcomb  <<<260, 256>>>(rp_W3, rp_b3, Wkv);
  k_xe     <<<EDGES, 64>>>(nidx);
  k_gemm   <<<dim3(128, 4), 256>>>();
  k_attn   <<<NODES, 128>>>(Wout, out);
}

// round 3
// speedup vs baseline: 2.3015x; 2.3015x over previous
#include <cuda_runtime.h>
#include <cuda_bf16.h>
#include <math.h>
#include <stdint.h>

// Shapes (fixed)
#define NB    2
#define NN    256
#define NK    16
#define ND    64
#define NHID  128
#define NKVD  256
#define NODES 512
#define EDGES 8192
#define KAUG  4160          // 64*64 + 64 bias rows

// ---------------- scratch ----------------
__device__ float g_x[NODES*ND];
__device__ float g_q[NODES*NHID];
__device__ float g_xi[NODES*ND];
__device__ float g_xj[NODES*ND];
__device__ float g_hdd[EDGES*64];
__device__ float g_xe[EDGES*ND];
__device__ __align__(128) __nv_bfloat16 g_wtH[NKVD*KAUG];   // [o2][kaug], hi split
__device__ __align__(128) __nv_bfloat16 g_wtL[NKVD*KAUG];   // lo split
__device__ float g_kv[EDGES*NKVD];
__device__ float g_maskf[EDGES];

__device__ __forceinline__ float blocksum64(float v, volatile float* sbuf, int t){
  #pragma unroll
  for (int o = 16; o; o >>= 1) v += __shfl_xor_sync(0xffffffffu, v, o);
  __syncthreads();
  if ((t & 31) == 0) sbuf[t >> 5] = v;
  __syncthreads();
  return sbuf[0] + sbuf[1];
}
__device__ __forceinline__ float silu(float x){ return x / (1.f + expf(-x)); }

// ---------------- mask dtype detection ----------------
__global__ void k_mask(const unsigned char* __restrict__ mraw){
  __shared__ int flags[2];
  int t = threadIdx.x;
  if (t < 2) flags[t] = 0;
  __syncthreads();
  int f3 = 0, fn = 0;
  for (int i = t; i < EDGES; i += 256){
    unsigned char bb = mraw[i];
    if (bb == 0x3fu) f3 = 1;
    if ((i & 3) && bb) fn = 1;
  }
  if (f3) atomicOr(&flags[0], 1);
  if (fn) atomicOr(&flags[1], 1);
  __syncthreads();
  int mode = flags[0] ? 2 : (flags[1] ? 0 : 1);
  for (int i = t; i < EDGES; i += 256){
    float m;
    if (mode == 2)      m = (((const float*)mraw)[i] != 0.f) ? 1.f : 0.f;
    else if (mode == 1) m = (((const int*)  mraw)[i] != 0  ) ? 1.f : 0.f;
    else                m = (mraw[i] != 0) ? 1.f : 0.f;
    g_maskf[i] = m;
  }
}

// ---------------- prenorm ----------------
__global__ void k_prenorm(const float* __restrict__ f, const float* __restrict__ nscale){
  __shared__ float sbuf[2];
  int node = blockIdx.x, t = threadIdx.x;
  float v  = f[node*ND + t];
  float ss = blocksum64(v*v, sbuf, t);
  float rms = sqrtf(ss) * 0.125f;
  float den = fmaxf(rms, 1e-12f);
  g_x[node*ND + t] = v / den * nscale[t];
}

// ---------------- q / xi / xj ----------------
__global__ void k_proj(const float* __restrict__ Wq, const float* __restrict__ Wxi,
                       const float* __restrict__ Wxj){
  __shared__ float sx[ND];
  int node = blockIdx.x, t = threadIdx.x;
  if (t < ND) sx[t] = g_x[node*ND + t];
  __syncthreads();
  if (t < NHID){
    float a = 0.f;
    #pragma unroll
    for (int d = 0; d < ND; d++) a = fmaf(sx[d], Wq[d*NHID + t], a);
    g_q[node*NHID + t] = a;
  } else if (t < NHID + ND){
    int c = t - NHID; float a = 0.f;
    #pragma unroll
    for (int d = 0; d < ND; d++) a = fmaf(sx[d], Wxi[d*ND + c], a);
    g_xi[node*ND + c] = a;
  } else {
    int c = t - NHID - ND; float a = 0.f;
    #pragma unroll
    for (int d = 0; d < ND; d++) a = fmaf(sx[d], Wxj[d*ND + c], a);
    g_xj[node*ND + c] = a;
  }
}

// ---------------- radial MLP ----------------
__global__ void k_radial(const float* __restrict__ rel,
                         const float* __restrict__ W1, const float* __restrict__ b1,
                         const float* __restrict__ g1, const float* __restrict__ W2,
                         const float* __restrict__ b2, const float* __restrict__ g2){
  __shared__ float sh[64];
  __shared__ float sbuf[2];
  int e = blockIdx.x, t = threadIdx.x;
  float r = rel[e];
  float h = silu(fmaf(r, W1[t], b1[t]));
  float mu  = blocksum64(h, sbuf, t) * (1.f/64.f);
  float c   = h - mu;
  float var = blocksum64(c*c, sbuf, t) * (1.f/64.f);
  h = c * rsqrtf(var + 1e-5f) * g1[t];
  sh[t] = h;
  __syncthreads();
  float h2 = b2[t];
  #pragma unroll
  for (int i = 0; i < 64; i++) h2 = fmaf(sh[i], W2[i*64 + t], h2);
  h2 = silu(h2);
  float mu2  = blocksum64(h2, sbuf, t) * (1.f/64.f);
  float c2   = h2 - mu2;
  float var2 = blocksum64(c2*c2, sbuf, t) * (1.f/64.f);
  g_hdd[e*64 + t] = c2 * rsqrtf(var2 + 1e-5f) * g2[t];
}

// ---------------- Wcomb = (W3-gather || b3) @ Wkv, transposed + bf16 split ----------------
__global__ void k_wcomb(const float* __restrict__ W3, const float* __restrict__ b3,
                        const float* __restrict__ Wkv){
  __shared__ float w3s[16][256];
  int c0 = blockIdx.x * 16;
  int t  = threadIdx.x;
  #pragma unroll
  for (int cc = 0; cc < 16; cc++){
    int c = c0 + cc;
    float v;
    if (c < 4096){
      int r = c >> 6, d = c & 63;
      v = W3[r*16384 + t*64 + d];
    } else {
      int d = c - 4096;
      v = b3[t*64 + d];
    }
    w3s[cc][t] = v;
  }
  __syncthreads();
  float acc[16];
  #pragma unroll
  for (int cc = 0; cc < 16; cc++) acc[cc] = 0.f;
  for (int o = 0; o < 256; o++){
    float wv = Wkv[o*256 + t];
    #pragma unroll
    for (int cc = 0; cc < 16; cc++) acc[cc] = fmaf(w3s[cc][o], wv, acc[cc]);
  }
  #pragma unroll
  for (int cc = 0; cc < 16; cc++){
    float a = acc[cc];
    __nv_bfloat16 hb = __float2bfloat16(a);
    float hf = __bfloat162float(hb);
    __nv_bfloat16 lb = __float2bfloat16(a - hf);
    g_wtH[(size_t)t*KAUG + c0 + cc] = hb;
    g_wtL[(size_t)t*KAUG + c0 + cc] = lb;
  }
}

// ---------------- xe ----------------
__global__ void k_xe(const int* __restrict__ nidx){
  int e = blockIdx.x, t = threadIdx.x;
  int node = e >> 4;
  int b    = node >> 8;
  int nb   = b*NN + nidx[e];
  g_xe[e*ND + t] = g_xj[nb*ND + t] + g_xi[node*ND + t];
}

// ================= mma.sync GEMM =================
// kv[8192,256] = P_aug @ Wcomb, fp32-split bf16, 3 products (AhBh+AhBl+AlBh).
// CTA tile 128x128, K-chunk 64, double buffered. 8 warps, each 32m x 64n.
// SMEM layout (bytes):
//   A tiles: [stage][split] 4 x 18432  at 0       (128 rows x stride 72 bf16)
//   B tiles: [stage][split] 4 x 18432  at 73728
//   hdd:     128 x 65 f32              at 147456
#define ATILE 18432
#define BOFF  73728
#define HOFF  147456
#define SMTOT 180736
#define SSTR  72

static __device__ __forceinline__ void cpasync16(unsigned sm, const void* g){
  asm volatile("cp.async.cg.shared.global [%0], [%1], 16;" :: "r"(sm), "l"(g));
}
static __device__ __forceinline__ void ldsm4(unsigned* r, unsigned addr){
  asm volatile("ldmatrix.sync.aligned.m8n8.x4.shared.b16 {%0,%1,%2,%3}, [%4];"
               : "=r"(r[0]), "=r"(r[1]), "=r"(r[2]), "=r"(r[3]) : "r"(addr));
}
static __device__ __forceinline__ void mma16816(float* c, const unsigned* a, const unsigned* b){
  asm volatile(
    "mma.sync.aligned.m16n8k16.row.col.f32.bf16.bf16.f32 "
    "{%0,%1,%2,%3}, {%4,%5,%6,%7}, {%8,%9}, {%0,%1,%2,%3};"
    : "+f"(c[0]), "+f"(c[1]), "+f"(c[2]), "+f"(c[3])
    : "r"(a[0]), "r"(a[1]), "r"(a[2]), "r"(a[3]), "r"(b[0]), "r"(b[1]));
}

__global__ void __launch_bounds__(256, 1) k_gemm(){
  extern __shared__ __align__(16) char smem[];
  const unsigned sbase = (unsigned)__cvta_generic_to_shared(smem);
  float* sHdd = (float*)(smem + HOFF);

  const int tid  = threadIdx.x;
  const int lane = tid & 31;
  const int wid  = tid >> 5;
  const int wm   = wid & 3;         // m warp: 0..3 -> rows wm*32
  const int wn   = wid >> 2;        // n warp: 0..1 -> cols wn*64
  const int m0   = blockIdx.x * 128;
  const int n0   = blockIdx.y * 128;

  // stage hdd [128][65]
  #pragma unroll
  for (int i = 0; i < 32; i++){
    int idx = tid + i*256;
    int row = idx >> 6, c = idx & 63;
    sHdd[row*65 + c] = g_hdd[(size_t)(m0+row)*64 + c];
  }
  // per-thread xe slice: row = tid>>1, 32 cols
  const int arow  = tid >> 1;
  const int halfc = (tid & 1) * 32;
  float xev[32];
  {
    const float* src = g_xe + (size_t)(m0+arow)*64 + halfc;
    #pragma unroll
    for (int j = 0; j < 32; j++) xev[j] = src[j];
  }
  __syncthreads();

  const __nv_bfloat16* wB[2] = { g_wtH + (size_t)n0*KAUG, g_wtL + (size_t)n0*KAUG };

  // ---- helpers as lambdas ----
  auto loadB = [&](int s, int kbase){
    #pragma unroll
    for (int p = 0; p < 2; p++){
      const __nv_bfloat16* w = wB[p];
      unsigned sm0 = sbase + BOFF + (unsigned)(s*2+p)*ATILE;
      #pragma unroll
      for (int i = 0; i < 4; i++){
        int q = tid + i*256;
        int row = q >> 3, w8 = q & 7;
        cpasync16(sm0 + (unsigned)(row*SSTR + w8*8)*2,
                  w + (size_t)row*KAUG + kbase + w8*8);
      }
    }
  };
  auto buildA = [&](int s, int r){
    float h = (r < 64) ? sHdd[arow*65 + r] : 1.0f;
    char* aHi = smem + (s*2+0)*ATILE;
    char* aLo = smem + (s*2+1)*ATILE;
    unsigned off = (unsigned)(arow*SSTR + halfc)*2;
    #pragma unroll
    for (int c = 0; c < 4; c++){
      uint4 hv, lv;
      unsigned* hp = (unsigned*)&hv;
      unsigned* lp = (unsigned*)&lv;
      #pragma unroll
      for (int m = 0; m < 4; m++){
        float v0 = h * xev[c*8 + 2*m];
        float v1 = h * xev[c*8 + 2*m + 1];
        __nv_bfloat162 hh = __floats2bfloat162_rn(v0, v1);
        unsigned hb = *(unsigned*)&hh;
        float h0 = __uint_as_float(hb << 16);
        float h1 = __uint_as_float(hb & 0xFFFF0000u);
        __nv_bfloat162 ll = __floats2bfloat162_rn(v0 - h0, v1 - h1);
        hp[m] = hb;
        lp[m] = *(unsigned*)&ll;
      }
      *(uint4*)(aHi + off + c*16) = hv;
      *(uint4*)(aLo + off + c*16) = lv;
    }
  };

  float acc[2][8][4];
  #pragma unroll
  for (int i = 0; i < 2; i++)
    #pragma unroll
    for (int j = 0; j < 8; j++)
      #pragma unroll
      for (int q = 0; q < 4; q++) acc[i][j][q] = 0.f;

  // prologue
  loadB(0, 0);
  asm volatile("cp.async.commit_group;" ::: "memory");
  buildA(0, 0);

  for (int r = 0; r <= 64; r++){
    const int s = r & 1;
    if (r < 64){
      int kb = (r + 1 < 64) ? (r + 1)*64 : 4096;
      loadB(s ^ 1, kb);
      asm volatile("cp.async.commit_group;" ::: "memory");
      buildA(s ^ 1, r + 1);
      asm volatile("cp.async.wait_group 1;" ::: "memory");
    } else {
      asm volatile("cp.async.wait_group 0;" ::: "memory");
    }
    __syncthreads();

    // 3 products: (Ah,Bh), (Ah,Bl), (Al,Bh)
    #pragma unroll
    for (int p = 0; p < 3; p++){
      const unsigned aBase = sbase + (unsigned)(s*2 + (p == 2 ? 1 : 0))*ATILE;
      const unsigned bBase = sbase + BOFF + (unsigned)(s*2 + (p == 1 ? 1 : 0))*ATILE;
      #pragma unroll
      for (int ks = 0; ks < 4; ks++){
        const int kk = ks*16;
        unsigned a[2][4];
        #pragma unroll
        for (int mi = 0; mi < 2; mi++){
          unsigned addr = aBase +
            (unsigned)((wm*32 + mi*16 + (lane & 15))*SSTR + kk + ((lane >> 4) << 3))*2;
          ldsm4(a[mi], addr);
        }
        unsigned b[4][4];
        #pragma unroll
        for (int ng = 0; ng < 4; ng++){
          int nb = wn*64 + ng*16;
          unsigned addr = bBase +
            (unsigned)((nb + (lane & 7) + ((lane >> 4) << 3))*SSTR + kk + (((lane >> 3) & 1) << 3))*2;
          ldsm4(b[ng], addr);
        }
        #pragma unroll
        for (int mi = 0; mi < 2; mi++)
          #pragma unroll
          for (int ng = 0; ng < 4; ng++){
            mma16816(acc[mi][2*ng+0], a[mi], &b[ng][0]);
            mma16816(acc[mi][2*ng+1], a[mi], &b[ng][2]);
          }
      }
    }
    __syncthreads();
  }

  // epilogue
  #pragma unroll
  for (int mi = 0; mi < 2; mi++){
    int row = m0 + wm*32 + mi*16 + (lane >> 2);
    #pragma unroll
    for (int nj = 0; nj < 8; nj++){
      int col = n0 + wn*64 + nj*8 + (lane & 3)*2;
      float* d = g_kv + (size_t)row*NKVD + col;
      *(float2*)d = make_float2(acc[mi][nj][0], acc[mi][nj][1]);
      *(float2*)(d + 8*NKVD) = make_float2(acc[mi][nj][2], acc[mi][nj][3]);
    }
  }
}

// ---------------- attention + out projection ----------------
__global__ void k_attn(const float* __restrict__ Wout, float* __restrict__ out){
  __shared__ float s_out[NHID];
  int node = blockIdx.x;
  int tid  = threadIdx.x;
  float qv = g_q[node*NHID + tid];

  float sim[NK];
  #pragma unroll
  for (int j = 0; j < NK; j++){
    int e = node*NK + j;
    float kvv = g_kv[(size_t)e*NKVD + tid];
    float dff = qv - kvv + 1e-6f;
    float s = dff * dff;
    #pragma unroll
    for (int o = 16; o; o >>= 1) s += __shfl_xor_sync(0xffffffffu, s, o);
    float m = g_maskf[e];
    sim[j] = (m != 0.f) ? (-sqrtf(s) * 0.17677669529663687f) : -3.402823466e38f;
  }
  float mx = sim[0];
  #pragma unroll
  for (int j = 1; j < NK; j++) mx = fmaxf(mx, sim[j]);
  float p[NK], den = 0.f;
  #pragma unroll
  for (int j = 0; j < NK; j++){ p[j] = expf(sim[j] - mx); den += p[j]; }
  float o = 0.f;
  #pragma unroll
  for (int j = 0; j < NK; j++){
    int e = node*NK + j;
    o = fmaf(p[j], g_kv[(size_t)e*NKVD + NHID + tid], o);
  }
  s_out[tid] = o / den;
  __syncthreads();
  if (tid < ND){
    float a = 0.f;
    #pragma unroll
    for (int c = 0; c < NHID; c++) a = fmaf(s_out[c], Wout[c*ND + tid], a);
    out[node*ND + tid] = a;
  }
}

// ---------------- launch ----------------
extern "C" void kernel_launch(void* const* d_in, const int* in_sizes, int n_in,
                              void* d_out, int out_size){
  const float* features = (const float*)d_in[0];
  const int*   nidx     = (const int*)  d_in[1];
  const unsigned char* mask = (const unsigned char*)d_in[2];
  const float* rel      = (const float*)d_in[3];
  const float* nscale   = (const float*)d_in[4];
  const float* Wq       = (const float*)d_in[5];
  const float* Wxi      = (const float*)d_in[6];
  const float* Wxj      = (const float*)d_in[7];
  const float* rp_W1    = (const float*)d_in[8];
  const float* rp_b1    = (const float*)d_in[9];
  const float* rp_g1    = (const float*)d_in[10];
  const float* rp_W2    = (const float*)d_in[11];
  const float* rp_b2    = (const float*)d_in[12];
  const float* rp_g2    = (const float*)d_in[13];
  const float* rp_W3    = (const float*)d_in[14];
  const float* rp_b3    = (const float*)d_in[15];
  const float* Wkv      = (const float*)d_in[16];
  const float* Wout     = (const float*)d_in[17];
  float* out = (float*)d_out;

  cudaFuncSetAttribute(k_gemm, cudaFuncAttributeMaxDynamicSharedMemorySize, SMTOT);

  k_mask   <<<1, 256>>>(mask);
  k_prenorm<<<NODES, 64>>>(features, nscale);
  k_proj   <<<NODES, 256>>>(Wq, Wxi, Wxj);
  k_radial <<<EDGES, 64>>>(rel, rp_W1, rp_b1, rp_g1, rp_W2, rp_b2, rp_g2);
  k_wcomb  <<<260, 256>>>(rp_W3, rp_b3, Wkv);
  k_xe     <<<EDGES, 64>>>(nidx);
  k_gemm   <<<dim3(64, 2), 256, SMTOT>>>();
  k_attn   <<<NODES, 128>>>(Wout, out);
}

// round 4
// speedup vs baseline: 3.0792x; 1.3379x over previous
#include <cuda_runtime.h>
#include <cuda_bf16.h>
#include <cuda_fp16.h>
#include <math.h>
#include <stdint.h>

// Shapes (fixed)
#define NB    2
#define NN    256
#define NK    16
#define ND    64
#define NHID  128
#define NKVD  256
#define NODES 512
#define EDGES 8192
#define KAUG  4160          // 64*64 + 64 bias rows

// ---------------- scratch ----------------
__device__ float g_x[NODES*ND];
__device__ float g_q[NODES*NHID];
__device__ float g_xi[NODES*ND];
__device__ float g_xj[NODES*ND];
__device__ float g_hdd[EDGES*64];
__device__ float g_xe[EDGES*ND];
__device__ __align__(128) __half g_wt[NKVD*KAUG];   // [o2][kaug], fp16
__device__ float g_kv[EDGES*NKVD];
__device__ float g_maskf[EDGES];

__device__ __forceinline__ float blocksum64(float v, volatile float* sbuf, int t){
  #pragma unroll
  for (int o = 16; o; o >>= 1) v += __shfl_xor_sync(0xffffffffu, v, o);
  __syncthreads();
  if ((t & 31) == 0) sbuf[t >> 5] = v;
  __syncthreads();
  return sbuf[0] + sbuf[1];
}
__device__ __forceinline__ float silu(float x){ return x / (1.f + expf(-x)); }

// ---------------- mask dtype detection ----------------
__global__ void k_mask(const unsigned char* __restrict__ mraw){
  __shared__ int flags[2];
  int t = threadIdx.x;
  if (t < 2) flags[t] = 0;
  __syncthreads();
  int f3 = 0, fn = 0;
  for (int i = t; i < EDGES; i += 256){
    unsigned char bb = mraw[i];
    if (bb == 0x3fu) f3 = 1;
    if ((i & 3) && bb) fn = 1;
  }
  if (f3) atomicOr(&flags[0], 1);
  if (fn) atomicOr(&flags[1], 1);
  __syncthreads();
  int mode = flags[0] ? 2 : (flags[1] ? 0 : 1);
  for (int i = t; i < EDGES; i += 256){
    float m;
    if (mode == 2)      m = (((const float*)mraw)[i] != 0.f) ? 1.f : 0.f;
    else if (mode == 1) m = (((const int*)  mraw)[i] != 0  ) ? 1.f : 0.f;
    else                m = (mraw[i] != 0) ? 1.f : 0.f;
    g_maskf[i] = m;
  }
}

// ---------------- prenorm ----------------
__global__ void k_prenorm(const float* __restrict__ f, const float* __restrict__ nscale){
  __shared__ float sbuf[2];
  int node = blockIdx.x, t = threadIdx.x;
  float v  = f[node*ND + t];
  float ss = blocksum64(v*v, sbuf, t);
  float rms = sqrtf(ss) * 0.125f;
  float den = fmaxf(rms, 1e-12f);
  g_x[node*ND + t] = v / den * nscale[t];
}

// ---------------- q / xi / xj ----------------
__global__ void k_proj(const float* __restrict__ Wq, const float* __restrict__ Wxi,
                       const float* __restrict__ Wxj){
  __shared__ float sx[ND];
  int node = blockIdx.x, t = threadIdx.x;
  if (t < ND) sx[t] = g_x[node*ND + t];
  __syncthreads();
  if (t < NHID){
    float a = 0.f;
    #pragma unroll
    for (int d = 0; d < ND; d++) a = fmaf(sx[d], Wq[d*NHID + t], a);
    g_q[node*NHID + t] = a;
  } else if (t < NHID + ND){
    int c = t - NHID; float a = 0.f;
    #pragma unroll
    for (int d = 0; d < ND; d++) a = fmaf(sx[d], Wxi[d*ND + c], a);
    g_xi[node*ND + c] = a;
  } else {
    int c = t - NHID - ND; float a = 0.f;
    #pragma unroll
    for (int d = 0; d < ND; d++) a = fmaf(sx[d], Wxj[d*ND + c], a);
    g_xj[node*ND + c] = a;
  }
}

// ---------------- radial MLP: warp-per-edge, shuffle-only reductions ----------------
__global__ void __launch_bounds__(256) k_radial(
    const float* __restrict__ rel,
    const float* __restrict__ W1, const float* __restrict__ b1,
    const float* __restrict__ g1, const float* __restrict__ W2,
    const float* __restrict__ b2, const float* __restrict__ g2){
  __shared__ float sW2[64][64];
  __shared__ float shh[8][64];
  int tid = threadIdx.x;
  int w   = tid >> 5;
  int lane= tid & 31;
  #pragma unroll
  for (int i = 0; i < 16; i++) ((float*)sW2)[tid + i*256] = W2[tid + i*256];
  __syncthreads();

  int e = blockIdx.x*8 + w;
  int c0 = lane, c1 = lane + 32;
  float r = rel[e];
  float h0 = silu(fmaf(r, W1[c0], b1[c0]));
  float h1 = silu(fmaf(r, W1[c1], b1[c1]));
  float s = h0 + h1;
  #pragma unroll
  for (int o = 16; o; o >>= 1) s += __shfl_xor_sync(0xffffffffu, s, o);
  float mu = s * (1.f/64.f);
  float d0 = h0 - mu, d1 = h1 - mu;
  float v = d0*d0 + d1*d1;
  #pragma unroll
  for (int o = 16; o; o >>= 1) v += __shfl_xor_sync(0xffffffffu, v, o);
  float rs = rsqrtf(v*(1.f/64.f) + 1e-5f);
  h0 = d0*rs*g1[c0];
  h1 = d1*rs*g1[c1];
  shh[w][c0] = h0;
  shh[w][c1] = h1;
  __syncwarp();
  float a0 = b2[c0], a1 = b2[c1];
  #pragma unroll
  for (int i = 0; i < 64; i++){
    float hv = shh[w][i];
    a0 = fmaf(hv, sW2[i][c0], a0);
    a1 = fmaf(hv, sW2[i][c1], a1);
  }
  a0 = silu(a0); a1 = silu(a1);
  s = a0 + a1;
  #pragma unroll
  for (int o = 16; o; o >>= 1) s += __shfl_xor_sync(0xffffffffu, s, o);
  mu = s * (1.f/64.f);
  d0 = a0 - mu; d1 = a1 - mu;
  v = d0*d0 + d1*d1;
  #pragma unroll
  for (int o = 16; o; o >>= 1) v += __shfl_xor_sync(0xffffffffu, v, o);
  rs = rsqrtf(v*(1.f/64.f) + 1e-5f);
  g_hdd[e*64 + c0] = d0*rs*g2[c0];
  g_hdd[e*64 + c1] = d1*rs*g2[c1];
}

// ---------------- Wcomb = (W3-gather || b3) @ Wkv, transposed, fp16 ----------------
__global__ void k_wcomb(const float* __restrict__ W3, const float* __restrict__ b3,
                        const float* __restrict__ Wkv){
  __shared__ float w3s[16][256];
  int c0 = blockIdx.x * 16;
  int t  = threadIdx.x;
  #pragma unroll
  for (int cc = 0; cc < 16; cc++){
    int c = c0 + cc;
    float v;
    if (c < 4096){
      int r = c >> 6, d = c & 63;
      v = W3[r*16384 + t*64 + d];
    } else {
      int d = c - 4096;
      v = b3[t*64 + d];
    }
    w3s[cc][t] = v;
  }
  __syncthreads();
  float acc[16];
  #pragma unroll
  for (int cc = 0; cc < 16; cc++) acc[cc] = 0.f;
  for (int o = 0; o < 256; o++){
    float wv = Wkv[o*256 + t];
    #pragma unroll
    for (int cc = 0; cc < 16; cc++) acc[cc] = fmaf(w3s[cc][o], wv, acc[cc]);
  }
  #pragma unroll
  for (int cc = 0; cc < 16; cc++)
    g_wt[(size_t)t*KAUG + c0 + cc] = __float2half_rn(acc[cc]);
}

// ---------------- xe ----------------
__global__ void k_xe(const int* __restrict__ nidx){
  int e = blockIdx.x, t = threadIdx.x;
  int node = e >> 4;
  int b    = node >> 8;
  int nb   = b*NN + nidx[e];
  g_xe[e*ND + t] = g_xj[nb*ND + t] + g_xi[node*ND + t];
}

// ================= mma.sync GEMM (fp16 A-split, 2 products) =================
// kv[8192,256] = P_aug @ Wcomb.  A = Ah + Al (fp16 split), B single fp16.
// CTA tile 128x128, K-chunk 64, double buffered. 8 warps, each 32m x 64n.
// SMEM (bytes): A [stage][split] 4 x 18432 at 0; B [stage] 2 x 18432 at 73728;
//               hdd 128x65 f32 at 110592.  Total 143872.
#define ATILE 18432
#define BOFF  73728
#define HOFF  110592
#define SMTOT 143872
#define SSTR  72

static __device__ __forceinline__ void cpasync16(unsigned sm, const void* g){
  asm volatile("cp.async.cg.shared.global [%0], [%1], 16;" :: "r"(sm), "l"(g));
}
static __device__ __forceinline__ void ldsm4(unsigned* r, unsigned addr){
  asm volatile("ldmatrix.sync.aligned.m8n8.x4.shared.b16 {%0,%1,%2,%3}, [%4];"
               : "=r"(r[0]), "=r"(r[1]), "=r"(r[2]), "=r"(r[3]) : "r"(addr));
}
static __device__ __forceinline__ void mma16816(float* c, const unsigned* a, const unsigned* b){
  asm volatile(
    "mma.sync.aligned.m16n8k16.row.col.f32.f16.f16.f32 "
    "{%0,%1,%2,%3}, {%4,%5,%6,%7}, {%8,%9}, {%0,%1,%2,%3};"
    : "+f"(c[0]), "+f"(c[1]), "+f"(c[2]), "+f"(c[3])
    : "r"(a[0]), "r"(a[1]), "r"(a[2]), "r"(a[3]), "r"(b[0]), "r"(b[1]));
}

__global__ void __launch_bounds__(256, 1) k_gemm(){
  extern __shared__ __align__(16) char smem[];
  const unsigned sbase = (unsigned)__cvta_generic_to_shared(smem);
  float* sHdd = (float*)(smem + HOFF);

  const int tid  = threadIdx.x;
  const int lane = tid & 31;
  const int wid  = tid >> 5;
  const int wm   = wid & 3;
  const int wn   = wid >> 2;
  const int m0   = blockIdx.x * 128;
  const int n0   = blockIdx.y * 128;

  #pragma unroll
  for (int i = 0; i < 32; i++){
    int idx = tid + i*256;
    int row = idx >> 6, c = idx & 63;
    sHdd[row*65 + c] = g_hdd[(size_t)(m0+row)*64 + c];
  }
  const int arow  = tid >> 1;
  const int halfc = (tid & 1) * 32;
  float xev[32];
  {
    const float* src = g_xe + (size_t)(m0+arow)*64 + halfc;
    #pragma unroll
    for (int j = 0; j < 32; j++) xev[j] = src[j];
  }
  __syncthreads();

  const __half* wB = g_wt + (size_t)n0*KAUG;

  auto loadB = [&](int s, int kbase){
    unsigned sm0 = sbase + BOFF + (unsigned)s*ATILE;
    #pragma unroll
    for (int i = 0; i < 4; i++){
      int q = tid + i*256;
      int row = q >> 3, w8 = q & 7;
      cpasync16(sm0 + (unsigned)(row*SSTR + w8*8)*2,
                wB + (size_t)row*KAUG + kbase + w8*8);
    }
  };
  auto buildA = [&](int s, int r){
    float h = (r < 64) ? sHdd[arow*65 + r] : 1.0f;
    char* aHi = smem + (s*2+0)*ATILE;
    char* aLo = smem + (s*2+1)*ATILE;
    unsigned off = (unsigned)(arow*SSTR + halfc)*2;
    #pragma unroll
    for (int c = 0; c < 4; c++){
      uint4 hv, lv;
      unsigned* hp = (unsigned*)&hv;
      unsigned* lp = (unsigned*)&lv;
      #pragma unroll
      for (int m = 0; m < 4; m++){
        float v0 = h * xev[c*8 + 2*m];
        float v1 = h * xev[c*8 + 2*m + 1];
        __half2 hh = __floats2half2_rn(v0, v1);
        float2 hf = __half22float2(hh);
        __half2 ll = __floats2half2_rn(v0 - hf.x, v1 - hf.y);
        hp[m] = *(unsigned*)&hh;
        lp[m] = *(unsigned*)&ll;
      }
      *(uint4*)(aHi + off + c*16) = hv;
      *(uint4*)(aLo + off + c*16) = lv;
    }
  };

  float acc[2][8][4];
  #pragma unroll
  for (int i = 0; i < 2; i++)
    #pragma unroll
    for (int j = 0; j < 8; j++)
      #pragma unroll
      for (int q = 0; q < 4; q++) acc[i][j][q] = 0.f;

  loadB(0, 0);
  asm volatile("cp.async.commit_group;" ::: "memory");
  buildA(0, 0);

  for (int r = 0; r <= 64; r++){
    const int s = r & 1;
    if (r < 64){
      int kb = (r + 1 < 64) ? (r + 1)*64 : 4096;
      loadB(s ^ 1, kb);
      asm volatile("cp.async.commit_group;" ::: "memory");
      buildA(s ^ 1, r + 1);
      asm volatile("cp.async.wait_group 1;" ::: "memory");
    } else {
      asm volatile("cp.async.wait_group 0;" ::: "memory");
    }
    __syncthreads();

    const unsigned aHiB = sbase + (unsigned)(s*2+0)*ATILE;
    const unsigned aLoB = sbase + (unsigned)(s*2+1)*ATILE;
    const unsigned bB   = sbase + BOFF + (unsigned)s*ATILE;
    #pragma unroll
    for (int ks = 0; ks < 4; ks++){
      const int kk = ks*16;
      unsigned ah[2][4], al[2][4], b[4][4];
      #pragma unroll
      for (int mi = 0; mi < 2; mi++){
        unsigned aoff =
          (unsigned)((wm*32 + mi*16 + (lane & 15))*SSTR + kk + ((lane >> 4) << 3))*2;
        ldsm4(ah[mi], aHiB + aoff);
        ldsm4(al[mi], aLoB + aoff);
      }
      #pragma unroll
      for (int ng = 0; ng < 4; ng++){
        int nb = wn*64 + ng*16;
        unsigned addr = bB +
          (unsigned)((nb + (lane & 7) + ((lane >> 4) << 3))*SSTR + kk + (((lane >> 3) & 1) << 3))*2;
        ldsm4(b[ng], addr);
      }
      #pragma unroll
      for (int mi = 0; mi < 2; mi++)
        #pragma unroll
        for (int ng = 0; ng < 4; ng++){
          mma16816(acc[mi][2*ng+0], ah[mi], &b[ng][0]);
          mma16816(acc[mi][2*ng+1], ah[mi], &b[ng][2]);
        }
      #pragma unroll
      for (int mi = 0; mi < 2; mi++)
        #pragma unroll
        for (int ng = 0; ng < 4; ng++){
          mma16816(acc[mi][2*ng+0], al[mi], &b[ng][0]);
          mma16816(acc[mi][2*ng+1], al[mi], &b[ng][2]);
        }
    }
    __syncthreads();
  }

  #pragma unroll
  for (int mi = 0; mi < 2; mi++){
    int row = m0 + wm*32 + mi*16 + (lane >> 2);
    #pragma unroll
    for (int nj = 0; nj < 8; nj++){
      int col = n0 + wn*64 + nj*8 + (lane & 3)*2;
      float* d = g_kv + (size_t)row*NKVD + col;
      *(float2*)d = make_float2(acc[mi][nj][0], acc[mi][nj][1]);
      *(float2*)(d + 8*NKVD) = make_float2(acc[mi][nj][2], acc[mi][nj][3]);
    }
  }
}

// ---------------- attention + out projection ----------------
__global__ void k_attn(const float* __restrict__ Wout, float* __restrict__ out){
  __shared__ float s_out[NHID];
  int node = blockIdx.x;
  int tid  = threadIdx.x;
  float qv = g_q[node*NHID + tid];

  float sim[NK];
  #pragma unroll
  for (int j = 0; j < NK; j++){
    int e = node*NK + j;
    float kvv = g_kv[(size_t)e*NKVD + tid];
    float dff = qv - kvv + 1e-6f;
    float s = dff * dff;
    #pragma unroll
    for (int o = 16; o; o >>= 1) s += __shfl_xor_sync(0xffffffffu, s, o);
    float m = g_maskf[e];
    sim[j] = (m != 0.f) ? (-sqrtf(s) * 0.17677669529663687f) : -3.402823466e38f;
  }
  float mx = sim[0];
  #pragma unroll
  for (int j = 1; j < NK; j++) mx = fmaxf(mx, sim[j]);
  float p[NK], den = 0.f;
  #pragma unroll
  for (int j = 0; j < NK; j++){ p[j] = expf(sim[j] - mx); den += p[j]; }
  float o = 0.f;
  #pragma unroll
  for (int j = 0; j < NK; j++){
    int e = node*NK + j;
    o = fmaf(p[j], g_kv[(size_t)e*NKVD + NHID + tid], o);
  }
  s_out[tid] = o / den;
  __syncthreads();
  if (tid < ND){
    float a = 0.f;
    #pragma unroll
    for (int c = 0; c < NHID; c++) a = fmaf(s_out[c], Wout[c*ND + tid], a);
    out[node*ND + tid] = a;
  }
}

// ---------------- launch ----------------
extern "C" void kernel_launch(void* const* d_in, const int* in_sizes, int n_in,
                              void* d_out, int out_size){
  const float* features = (const float*)d_in[0];
  const int*   nidx     = (const int*)  d_in[1];
  const unsigned char* mask = (const unsigned char*)d_in[2];
  const float* rel      = (const float*)d_in[3];
  const float* nscale   = (const float*)d_in[4];
  const float* Wq       = (const float*)d_in[5];
  const float* Wxi      = (const float*)d_in[6];
  const float* Wxj      = (const float*)d_in[7];
  const float* rp_W1    = (const float*)d_in[8];
  const float* rp_b1    = (const float*)d_in[9];
  const float* rp_g1    = (const float*)d_in[10];
  const float* rp_W2    = (const float*)d_in[11];
  const float* rp_b2    = (const float*)d_in[12];
  const float* rp_g2    = (const float*)d_in[13];
  const float* rp_W3    = (const float*)d_in[14];
  const float* rp_b3    = (const float*)d_in[15];
  const float* Wkv      = (const float*)d_in[16];
  const float* Wout     = (const float*)d_in[17];
  float* out = (float*)d_out;

  cudaFuncSetAttribute(k_gemm, cudaFuncAttributeMaxDynamicSharedMemorySize, SMTOT);

  k_mask   <<<1, 256>>>(mask);
  k_prenorm<<<NODES, 64>>>(features, nscale);
  k_proj   <<<NODES, 256>>>(Wq, Wxi, Wxj);
  k_radial <<<1024, 256>>>(rel, rp_W1, rp_b1, rp_g1, rp_W2, rp_b2, rp_g2);
  k_wcomb  <<<260, 256>>>(rp_W3, rp_b3, Wkv);
  k_xe     <<<EDGES, 64>>>(nidx);
  k_gemm   <<<dim3(64, 2), 256, SMTOT>>>();
  k_attn   <<<NODES, 128>>>(Wout, out);
}

// round 6
// speedup vs baseline: 4.1631x; 1.3520x over previous
#include <cuda_runtime.h>
#include <cuda_fp16.h>
#include <math.h>
#include <stdint.h>

// Shapes (fixed)
#define NB    2
#define NN    256
#define NK    16
#define ND    64
#define NHID  128
#define NKVD  256
#define NODES 512
#define EDGES 8192
#define KAUG  4160          // 64*64 + 64 bias rows

// ---------------- scratch ----------------
__device__ float g_q[NODES*NHID];
__device__ float g_xi[NODES*ND];
__device__ float g_xj[NODES*ND];
__device__ float g_hdd[EDGES*64];
__device__ __align__(128) __half g_wt[NKVD*KAUG];   // [o2][kaug], fp16
__device__ float g_kv[EDGES*NKVD];
__device__ float g_maskf[EDGES];

__device__ __forceinline__ float silu(float x){ return x / (1.f + expf(-x)); }

// ---------------- mask dtype detection ----------------
__global__ void k_mask(const unsigned char* __restrict__ mraw){
  __shared__ int flags[2];
  int t = threadIdx.x;
  if (t < 2) flags[t] = 0;
  __syncthreads();
  int f3 = 0, fn = 0;
  for (int i = t; i < EDGES; i += 256){
    unsigned char bb = mraw[i];
    if (bb == 0x3fu) f3 = 1;
    if ((i & 3) && bb) fn = 1;
  }
  if (f3) atomicOr(&flags[0], 1);
  if (fn) atomicOr(&flags[1], 1);
  __syncthreads();
  int mode = flags[0] ? 2 : (flags[1] ? 0 : 1);
  for (int i = t; i < EDGES; i += 256){
    float m;
    if (mode == 2)      m = (((const float*)mraw)[i] != 0.f) ? 1.f : 0.f;
    else if (mode == 1) m = (((const int*)  mraw)[i] != 0  ) ? 1.f : 0.f;
    else                m = (mraw[i] != 0) ? 1.f : 0.f;
    g_maskf[i] = m;
  }
}

// ---------------- fused prenorm + q/xi/xj projections ----------------
__global__ void __launch_bounds__(256) k_pre(
    const float* __restrict__ f, const float* __restrict__ nscale,
    const float* __restrict__ Wq, const float* __restrict__ Wxi,
    const float* __restrict__ Wxj){
  __shared__ float sv[ND];
  __shared__ float sx[ND];
  int node = blockIdx.x, t = threadIdx.x;
  if (t < ND) sv[t] = f[node*ND + t];
  __syncthreads();
  float ss = 0.f;
  #pragma unroll
  for (int d = 0; d < ND; d++) ss = fmaf(sv[d], sv[d], ss);
  float den = fmaxf(sqrtf(ss) * 0.125f, 1e-12f);
  if (t < ND) sx[t] = sv[t] / den * nscale[t];
  __syncthreads();
  if (t < NHID){
    float a = 0.f;
    #pragma unroll
    for (int d = 0; d < ND; d++) a = fmaf(sx[d], Wq[d*NHID + t], a);
    g_q[node*NHID + t] = a;
  } else if (t < NHID + ND){
    int c = t - NHID; float a = 0.f;
    #pragma unroll
    for (int d = 0; d < ND; d++) a = fmaf(sx[d], Wxi[d*ND + c], a);
    g_xi[node*ND + c] = a;
  } else {
    int c = t - NHID - ND; float a = 0.f;
    #pragma unroll
    for (int d = 0; d < ND; d++) a = fmaf(sx[d], Wxj[d*ND + c], a);
    g_xj[node*ND + c] = a;
  }
}

// ---------------- radial MLP: warp-per-edge, shuffle-only reductions ----------------
__global__ void __launch_bounds__(256) k_radial(
    const float* __restrict__ rel,
    const float* __restrict__ W1, const float* __restrict__ b1,
    const float* __restrict__ g1, const float* __restrict__ W2,
    const float* __restrict__ b2, const float* __restrict__ g2){
  __shared__ float sW2[64][64];
  __shared__ float shh[8][64];
  int tid = threadIdx.x;
  int w   = tid >> 5;
  int lane= tid & 31;
  #pragma unroll
  for (int i = 0; i < 16; i++) ((float*)sW2)[tid + i*256] = W2[tid + i*256];
  __syncthreads();

  int e = blockIdx.x*8 + w;
  int c0 = lane, c1 = lane + 32;
  float r = rel[e];
  float h0 = silu(fmaf(r, W1[c0], b1[c0]));
  float h1 = silu(fmaf(r, W1[c1], b1[c1]));
  float s = h0 + h1;
  #pragma unroll
  for (int o = 16; o; o >>= 1) s += __shfl_xor_sync(0xffffffffu, s, o);
  float mu = s * (1.f/64.f);
  float d0 = h0 - mu, d1 = h1 - mu;
  float v = d0*d0 + d1*d1;
  #pragma unroll
  for (int o = 16; o; o >>= 1) v += __shfl_xor_sync(0xffffffffu, v, o);
  float rs = rsqrtf(v*(1.f/64.f) + 1e-5f);
  h0 = d0*rs*g1[c0];
  h1 = d1*rs*g1[c1];
  shh[w][c0] = h0;
  shh[w][c1] = h1;
  __syncwarp();
  float a0 = b2[c0], a1 = b2[c1];
  #pragma unroll
  for (int i = 0; i < 64; i++){
    float hv = shh[w][i];
    a0 = fmaf(hv, sW2[i][c0], a0);
    a1 = fmaf(hv, sW2[i][c1], a1);
  }
  a0 = silu(a0); a1 = silu(a1);
  s = a0 + a1;
  #pragma unroll
  for (int o = 16; o; o >>= 1) s += __shfl_xor_sync(0xffffffffu, s, o);
  mu = s * (1.f/64.f);
  d0 = a0 - mu; d1 = a1 - mu;
  v = d0*d0 + d1*d1;
  #pragma unroll
  for (int o = 16; o; o >>= 1) v += __shfl_xor_sync(0xffffffffu, v, o);
  rs = rsqrtf(v*(1.f/64.f) + 1e-5f);
  g_hdd[e*64 + c0] = d0*rs*g2[c0];
  g_hdd[e*64 + c1] = d1*rs*g2[c1];
}

// ---------------- Wcomb = (W3-gather || b3) @ Wkv, transposed, fp16 ----------------
__global__ void k_wcomb(const float* __restrict__ W3, const float* __restrict__ b3,
                        const float* __restrict__ Wkv){
  __shared__ float w3s[16][256];
  int c0 = blockIdx.x * 16;
  int t  = threadIdx.x;
  #pragma unroll
  for (int cc = 0; cc < 16; cc++){
    int c = c0 + cc;
    float v;
    if (c < 4096){
      int r = c >> 6, d = c & 63;
      v = W3[r*16384 + t*64 + d];
    } else {
      int d = c - 4096;
      v = b3[t*64 + d];
    }
    w3s[cc][t] = v;
  }
  __syncthreads();
  float acc[16];
  #pragma unroll
  for (int cc = 0; cc < 16; cc++) acc[cc] = 0.f;
  for (int o = 0; o < 256; o++){
    float wv = Wkv[o*256 + t];
    #pragma unroll
    for (int cc = 0; cc < 16; cc++) acc[cc] = fmaf(w3s[cc][o], wv, acc[cc]);
  }
  #pragma unroll
  for (int cc = 0; cc < 16; cc++)
    g_wt[(size_t)t*KAUG + c0 + cc] = __float2half_rn(acc[cc]);
}

// ================= mma.sync GEMM (single fp16 product) =================
// kv[8192,256] = P_aug @ Wcomb.  A[e, r*64+d] = hdd[e,r]*xe[e,d] (+bias rows = xe).
// xe gathered inline: xe[e] = xj[nb] + xi[node].
// CTA tile 128x128, K-chunk 64, double buffered. 8 warps, each 32m x 64n.
// SMEM (bytes): A [stage] 2 x 18432 at 0; B [stage] 2 x 18432 at 36864;
//               hdd 128x65 f32 at 73728.  Total 107008.
#define ATILE 18432
#define BOFF  36864
#define HOFF  73728
#define SMTOT 107008
#define SSTR  72

static __device__ __forceinline__ void cpasync16(unsigned sm, const void* g){
  asm volatile("cp.async.cg.shared.global [%0], [%1], 16;" :: "r"(sm), "l"(g));
}
static __device__ __forceinline__ void ldsm4(unsigned* r, unsigned addr){
  asm volatile("ldmatrix.sync.aligned.m8n8.x4.shared.b16 {%0,%1,%2,%3}, [%4];"
               : "=r"(r[0]), "=r"(r[1]), "=r"(r[2]), "=r"(r[3]) : "r"(addr));
}
static __device__ __forceinline__ void mma16816(float* c, const unsigned* a, const unsigned* b){
  asm volatile(
    "mma.sync.aligned.m16n8k16.row.col.f32.f16.f16.f32 "
    "{%0,%1,%2,%3}, {%4,%5,%6,%7}, {%8,%9}, {%0,%1,%2,%3};"
    : "+f"(c[0]), "+f"(c[1]), "+f"(c[2]), "+f"(c[3])
    : "r"(a[0]), "r"(a[1]), "r"(a[2]), "r"(a[3]), "r"(b[0]), "r"(b[1]));
}

__global__ void __launch_bounds__(256, 1) k_gemm(const int* __restrict__ nidx){
  extern __shared__ __align__(16) char smem[];
  const unsigned sbase = (unsigned)__cvta_generic_to_shared(smem);
  float* sHdd = (float*)(smem + HOFF);

  const int tid  = threadIdx.x;
  const int lane = tid & 31;
  const int wid  = tid >> 5;
  const int wm   = wid & 3;
  const int wn   = wid >> 2;
  const int m0   = blockIdx.x * 128;
  const int n0   = blockIdx.y * 128;

  #pragma unroll
  for (int i = 0; i < 32; i++){
    int idx = tid + i*256;
    int row = idx >> 6, c = idx & 63;
    sHdd[row*65 + c] = g_hdd[(size_t)(m0+row)*64 + c];
  }
  // per-thread xe slice (gather fused): row = tid>>1, 32 cols
  const int arow  = tid >> 1;
  const int halfc = (tid & 1) * 32;
  float xev[32];
  {
    int e    = m0 + arow;
    int node = e >> 4;
    int b    = node >> 8;
    int nb   = b*NN + nidx[e];
    const float* pj = g_xj + (size_t)nb*ND + halfc;
    const float* pi = g_xi + (size_t)node*ND + halfc;
    #pragma unroll
    for (int j = 0; j < 32; j++) xev[j] = pj[j] + pi[j];
  }
  __syncthreads();

  const __half* wB = g_wt + (size_t)n0*KAUG;

  auto loadB = [&](int s, int kbase){
    unsigned sm0 = sbase + BOFF + (unsigned)s*ATILE;
    #pragma unroll
    for (int i = 0; i < 4; i++){
      int q = tid + i*256;
      int row = q >> 3, w8 = q & 7;
      cpasync16(sm0 + (unsigned)(row*SSTR + w8*8)*2,
                wB + (size_t)row*KAUG + kbase + w8*8);
    }
  };
  auto buildA = [&](int s, int r){
    float h = (r < 64) ? sHdd[arow*65 + r] : 1.0f;
    char* aT = smem + s*ATILE;
    unsigned off = (unsigned)(arow*SSTR + halfc)*2;
    #pragma unroll
    for (int c = 0; c < 4; c++){
      uint4 hv;
      unsigned* hp = (unsigned*)&hv;
      #pragma unroll
      for (int m = 0; m < 4; m++){
        __half2 hh = __floats2half2_rn(h * xev[c*8 + 2*m], h * xev[c*8 + 2*m + 1]);
        hp[m] = *(unsigned*)&hh;
      }
      *(uint4*)(aT + off + c*16) = hv;
    }
  };

  float acc[2][8][4];
  #pragma unroll
  for (int i = 0; i < 2; i++)
    #pragma unroll
    for (int j = 0; j < 8; j++)
      #pragma unroll
      for (int q = 0; q < 4; q++) acc[i][j][q] = 0.f;

  loadB(0, 0);
  asm volatile("cp.async.commit_group;" ::: "memory");
  buildA(0, 0);

  for (int r = 0; r <= 64; r++){
    const int s = r & 1;
    if (r < 64){
      int kb = (r + 1 < 64) ? (r + 1)*64 : 4096;
      loadB(s ^ 1, kb);
      asm volatile("cp.async.commit_group;" ::: "memory");
      buildA(s ^ 1, r + 1);
      asm volatile("cp.async.wait_group 1;" ::: "memory");
    } else {
      asm volatile("cp.async.wait_group 0;" ::: "memory");
    }
    __syncthreads();

    const unsigned aB = sbase + (unsigned)s*ATILE;
    const unsigned bB = sbase + BOFF + (unsigned)s*ATILE;
    #pragma unroll
    for (int ks = 0; ks < 4; ks++){
      const int kk = ks*16;
      unsigned a[2][4], b[4][4];
      #pragma unroll
      for (int mi = 0; mi < 2; mi++){
        unsigned aoff =
          (unsigned)((wm*32 + mi*16 + (lane & 15))*SSTR + kk + ((lane >> 4) << 3))*2;
        ldsm4(a[mi], aB + aoff);
      }
      #pragma unroll
      for (int ng = 0; ng < 4; ng++){
        int nb = wn*64 + ng*16;
        unsigned addr = bB +
          (unsigned)((nb + (lane & 7) + ((lane >> 4) << 3))*SSTR + kk + (((lane >> 3) & 1) << 3))*2;
        ldsm4(b[ng], addr);
      }
      #pragma unroll
      for (int mi = 0; mi < 2; mi++)
        #pragma unroll
        for (int ng = 0; ng < 4; ng++){
          mma16816(acc[mi][2*ng+0], a[mi], &b[ng][0]);
          mma16816(acc[mi][2*ng+1], a[mi], &b[ng][2]);
        }
    }
    __syncthreads();
  }

  #pragma unroll
  for (int mi = 0; mi < 2; mi++){
    int row = m0 + wm*32 + mi*16 + (lane >> 2);
    #pragma unroll
    for (int nj = 0; nj < 8; nj++){
      int col = n0 + wn*64 + nj*8 + (lane & 3)*2;
      float* d = g_kv + (size_t)row*NKVD + col;
      *(float2*)d = make_float2(acc[mi][nj][0], acc[mi][nj][1]);
      *(float2*)(d + 8*NKVD) = make_float2(acc[mi][nj][2], acc[mi][nj][3]);
    }
  }
}

// ---------------- attention + out projection ----------------
__global__ void k_attn(const float* __restrict__ Wout, float* __restrict__ out){
  __shared__ float s_out[NHID];
  int node = blockIdx.x;
  int tid  = threadIdx.x;
  float qv = g_q[node*NHID + tid];

  float sim[NK];
  #pragma unroll
  for (int j = 0; j < NK; j++){
    int e = node*NK + j;
    float kvv = g_kv[(size_t)e*NKVD + tid];
    float dff = qv - kvv + 1e-6f;
    float s = dff * dff;
    #pragma unroll
    for (int o = 16; o; o >>= 1) s += __shfl_xor_sync(0xffffffffu, s, o);
    float m = g_maskf[e];
    sim[j] = (m != 0.f) ? (-sqrtf(s) * 0.17677669529663687f) : -3.402823466e38f;
  }
  float mx = sim[0];
  #pragma unroll
  for (int j = 1; j < NK; j++) mx = fmaxf(mx, sim[j]);
  float p[NK], den = 0.f;
  #pragma unroll
  for (int j = 0; j < NK; j++){ p[j] = expf(sim[j] - mx); den += p[j]; }
  float o = 0.f;
  #pragma unroll
  for (int j = 0; j < NK; j++){
    int e = node*NK + j;
    o = fmaf(p[j], g_kv[(size_t)e*NKVD + NHID + tid], o);
  }
  s_out[tid] = o / den;
  __syncthreads();
  if (tid < ND){
    float a = 0.f;
    #pragma unroll
    for (int c = 0; c < NHID; c++) a = fmaf(s_out[c], Wout[c*ND + tid], a);
    out[node*ND + tid] = a;
  }
}

// ---------------- launch ----------------
extern "C" void kernel_launch(void* const* d_in, const int* in_sizes, int n_in,
                              void* d_out, int out_size){
  const float* features = (const float*)d_in[0];
  const int*   nidx     = (const int*)  d_in[1];
  const unsigned char* mask = (const unsigned char*)d_in[2];
  const float* rel      = (const float*)d_in[3];
  const float* nscale   = (const float*)d_in[4];
  const float* Wq       = (const float*)d_in[5];
  const float* Wxi      = (const float*)d_in[6];
  const float* Wxj      = (const float*)d_in[7];
  const float* rp_W1    = (const float*)d_in[8];
  const float* rp_b1    = (const float*)d_in[9];
  const float* rp_g1    = (const float*)d_in[10];
  const float* rp_W2    = (const float*)d_in[11];
  const float* rp_b2    = (const float*)d_in[12];
  const float* rp_g2    = (const float*)d_in[13];
  const float* rp_W3    = (const float*)d_in[14];
  const float* rp_b3    = (const float*)d_in[15];
  const float* Wkv      = (const float*)d_in[16];
  const float* Wout     = (const float*)d_in[17];
  float* out = (float*)d_out;

  cudaFuncSetAttribute(k_gemm, cudaFuncAttributeMaxDynamicSharedMemorySize, SMTOT);

  k_mask   <<<1, 256>>>(mask);
  k_pre    <<<NODES, 256>>>(features, nscale, Wq, Wxi, Wxj);
  k_radial <<<1024, 256>>>(rel, rp_W1, rp_b1, rp_g1, rp_W2, rp_b2, rp_g2);
  k_wcomb  <<<260, 256>>>(rp_W3, rp_b3, Wkv);
  k_gemm   <<<dim3(64, 2), 256, SMTOT>>>(nidx);
  k_attn   <<<NODES, 128>>>(Wout, out);
}

// round 7
// speedup vs baseline: 4.5835x; 1.1010x over previous
#include <cuda_runtime.h>
#include <cuda_fp16.h>
#include <math.h>
#include <stdint.h>

// Shapes (fixed)
#define NB    2
#define NN    256
#define NK    16
#define ND    64
#define NHID  128
#define NKVD  256
#define NODES 512
#define EDGES 8192
#define KAUG  4160          // 64*64 + 64 bias rows

// ---------------- scratch ----------------
__device__ float g_q[NODES*NHID];
__device__ float g_xi[NODES*ND];
__device__ float g_xj[NODES*ND];
__device__ float g_hdd[EDGES*64];
__device__ __align__(128) __half g_wt[NKVD*KAUG];   // [o2][kaug], fp16
__device__ float g_kv[EDGES*NKVD];
__device__ float g_maskf[EDGES];

__device__ __forceinline__ float silu(float x){ return x / (1.f + expf(-x)); }

// ---------------- fused prenorm + q/xi/xj projections + mask detect ----------------
__global__ void __launch_bounds__(256) k_pre(
    const float* __restrict__ f, const float* __restrict__ nscale,
    const float* __restrict__ Wq, const float* __restrict__ Wxi,
    const float* __restrict__ Wxj, const unsigned char* __restrict__ mraw){
  __shared__ float sv[ND];
  __shared__ float sx[ND];
  __shared__ int flags[2];
  int t = threadIdx.x;

  if (blockIdx.x == NODES){
    // mask dtype detection + expansion (bool serialization ambiguous)
    if (t < 2) flags[t] = 0;
    __syncthreads();
    int f3 = 0, fn = 0;
    for (int i = t; i < EDGES; i += 256){
      unsigned char bb = mraw[i];
      if (bb == 0x3fu) f3 = 1;
      if ((i & 3) && bb) fn = 1;
    }
    if (f3) atomicOr(&flags[0], 1);
    if (fn) atomicOr(&flags[1], 1);
    __syncthreads();
    int mode = flags[0] ? 2 : (flags[1] ? 0 : 1);
    for (int i = t; i < EDGES; i += 256){
      float m;
      if (mode == 2)      m = (((const float*)mraw)[i] != 0.f) ? 1.f : 0.f;
      else if (mode == 1) m = (((const int*)  mraw)[i] != 0  ) ? 1.f : 0.f;
      else                m = (mraw[i] != 0) ? 1.f : 0.f;
      g_maskf[i] = m;
    }
    return;
  }

  int node = blockIdx.x;
  if (t < ND) sv[t] = f[node*ND + t];
  __syncthreads();
  float ss = 0.f;
  #pragma unroll
  for (int d = 0; d < ND; d++) ss = fmaf(sv[d], sv[d], ss);
  float den = fmaxf(sqrtf(ss) * 0.125f, 1e-12f);
  if (t < ND) sx[t] = sv[t] / den * nscale[t];
  __syncthreads();
  if (t < NHID){
    float a = 0.f;
    #pragma unroll
    for (int d = 0; d < ND; d++) a = fmaf(sx[d], Wq[d*NHID + t], a);
    g_q[node*NHID + t] = a;
  } else if (t < NHID + ND){
    int c = t - NHID; float a = 0.f;
    #pragma unroll
    for (int d = 0; d < ND; d++) a = fmaf(sx[d], Wxi[d*ND + c], a);
    g_xi[node*ND + c] = a;
  } else {
    int c = t - NHID - ND; float a = 0.f;
    #pragma unroll
    for (int d = 0; d < ND; d++) a = fmaf(sx[d], Wxj[d*ND + c], a);
    g_xj[node*ND + c] = a;
  }
}

// ---------------- radial MLP: warp-per-edge, shuffle-only reductions ----------------
__global__ void __launch_bounds__(256) k_radial(
    const float* __restrict__ rel,
    const float* __restrict__ W1, const float* __restrict__ b1,
    const float* __restrict__ g1, const float* __restrict__ W2,
    const float* __restrict__ b2, const float* __restrict__ g2){
  __shared__ float sW2[64][64];
  __shared__ float shh[8][64];
  int tid = threadIdx.x;
  int w   = tid >> 5;
  int lane= tid & 31;
  #pragma unroll
  for (int i = 0; i < 16; i++) ((float*)sW2)[tid + i*256] = W2[tid + i*256];
  __syncthreads();

  int e = blockIdx.x*8 + w;
  int c0 = lane, c1 = lane + 32;
  float r = rel[e];
  float h0 = silu(fmaf(r, W1[c0], b1[c0]));
  float h1 = silu(fmaf(r, W1[c1], b1[c1]));
  float s = h0 + h1;
  #pragma unroll
  for (int o = 16; o; o >>= 1) s += __shfl_xor_sync(0xffffffffu, s, o);
  float mu = s * (1.f/64.f);
  float d0 = h0 - mu, d1 = h1 - mu;
  float v = d0*d0 + d1*d1;
  #pragma unroll
  for (int o = 16; o; o >>= 1) v += __shfl_xor_sync(0xffffffffu, v, o);
  float rs = rsqrtf(v*(1.f/64.f) + 1e-5f);
  h0 = d0*rs*g1[c0];
  h1 = d1*rs*g1[c1];
  shh[w][c0] = h0;
  shh[w][c1] = h1;
  __syncwarp();
  float a0 = b2[c0], a1 = b2[c1];
  #pragma unroll
  for (int i = 0; i < 64; i++){
    float hv = shh[w][i];
    a0 = fmaf(hv, sW2[i][c0], a0);
    a1 = fmaf(hv, sW2[i][c1], a1);
  }
  a0 = silu(a0); a1 = silu(a1);
  s = a0 + a1;
  #pragma unroll
  for (int o = 16; o; o >>= 1) s += __shfl_xor_sync(0xffffffffu, s, o);
  mu = s * (1.f/64.f);
  d0 = a0 - mu; d1 = a1 - mu;
  v = d0*d0 + d1*d1;
  #pragma unroll
  for (int o = 16; o; o >>= 1) v += __shfl_xor_sync(0xffffffffu, v, o);
  rs = rsqrtf(v*(1.f/64.f) + 1e-5f);
  g_hdd[e*64 + c0] = d0*rs*g2[c0];
  g_hdd[e*64 + c1] = d1*rs*g2[c1];
}

// ---------------- shared MMA helpers ----------------
static __device__ __forceinline__ void cpasync16(unsigned sm, const void* g){
  asm volatile("cp.async.cg.shared.global [%0], [%1], 16;" :: "r"(sm), "l"(g));
}
static __device__ __forceinline__ void ldsm4(unsigned* r, unsigned addr){
  asm volatile("ldmatrix.sync.aligned.m8n8.x4.shared.b16 {%0,%1,%2,%3}, [%4];"
               : "=r"(r[0]), "=r"(r[1]), "=r"(r[2]), "=r"(r[3]) : "r"(addr));
}
static __device__ __forceinline__ void mma16816(float* c, const unsigned* a, const unsigned* b){
  asm volatile(
    "mma.sync.aligned.m16n8k16.row.col.f32.f16.f16.f32 "
    "{%0,%1,%2,%3}, {%4,%5,%6,%7}, {%8,%9}, {%0,%1,%2,%3};"
    : "+f"(c[0]), "+f"(c[1]), "+f"(c[2]), "+f"(c[3])
    : "r"(a[0]), "r"(a[1]), "r"(a[2]), "r"(a[3]), "r"(b[0]), "r"(b[1]));
}

// ================= wcomb via mma.sync (hi/lo both operands, 3 products) =================
// g_wt[n][c] = sum_o Wkv[o][n] * W3aug[c][o],  c=(r,d): W3aug[c][o]=W3[r][o][d], bias=b3[o][d].
// Per CTA: r-block (65) x n-half (2).  M=128(n) x N=64(d), K=256(o), one-shot SMEM.
// Transpose at STS time (pack half2 along o); compute reuses proven k_gemm fragment code.
#define W_STR 264
#define W_AHI 0
#define W_ALO 67584
#define W_BHI 135168
#define W_BLO 168960
#define W_SMT 202752

__global__ void __launch_bounds__(256, 1) k_wcomb(
    const float* __restrict__ W3, const float* __restrict__ b3,
    const float* __restrict__ Wkv){
  extern __shared__ __align__(16) char smem[];
  const unsigned sbase = (unsigned)__cvta_generic_to_shared(smem);
  const int tid  = threadIdx.x;
  const int lane = tid & 31;
  const int wid  = tid >> 5;
  const int wm   = wid & 3;         // 4 m-warps (n dim), 32 rows each
  const int wn   = wid >> 2;        // 2 n-warps (d dim), 32 cols each
  const int r    = blockIdx.x;      // 0..64 (64 = bias block)
  const int n0   = blockIdx.y * 128;
  const float* srcB = (r < 64) ? (W3 + (size_t)r*16384) : b3;

  // ---- load A = Wkv^T half (transpose+split at STS) ----
  #pragma unroll
  for (int i = 0; i < 16; i++){
    int u = tid + i*256;
    int opair = u >> 5, f4 = u & 31;
    int o = opair*2, n = f4*4;
    float4 v0 = *(const float4*)(Wkv + (size_t)o*256 + n0 + n);
    float4 v1 = *(const float4*)(Wkv + (size_t)(o+1)*256 + n0 + n);
    const float* p0 = (const float*)&v0;
    const float* p1 = (const float*)&v1;
    #pragma unroll
    for (int j = 0; j < 4; j++){
      float x0 = p0[j], x1 = p1[j];
      __half h0 = __float2half_rn(x0), h1 = __float2half_rn(x1);
      __half l0 = __float2half_rn(x0 - __half2float(h0));
      __half l1 = __float2half_rn(x1 - __half2float(h1));
      __half2 hh; hh.x = h0; hh.y = h1;
      __half2 ll; ll.x = l0; ll.y = l1;
      unsigned off = (unsigned)((n + j)*W_STR + o)*2;
      *(__half2*)(smem + W_AHI + off) = hh;
      *(__half2*)(smem + W_ALO + off) = ll;
    }
  }
  // ---- load B = W3 block (transpose+split at STS) ----
  #pragma unroll
  for (int i = 0; i < 8; i++){
    int u = tid + i*256;
    int opair = u >> 4, f4 = u & 15;
    int o = opair*2, d = f4*4;
    float4 v0 = *(const float4*)(srcB + (size_t)o*64 + d);
    float4 v1 = *(const float4*)(srcB + (size_t)(o+1)*64 + d);
    const float* p0 = (const float*)&v0;
    const float* p1 = (const float*)&v1;
    #pragma unroll
    for (int j = 0; j < 4; j++){
      float x0 = p0[j], x1 = p1[j];
      __half h0 = __float2half_rn(x0), h1 = __float2half_rn(x1);
      __half l0 = __float2half_rn(x0 - __half2float(h0));
      __half l1 = __float2half_rn(x1 - __half2float(h1));
      __half2 hh; hh.x = h0; hh.y = h1;
      __half2 ll; ll.x = l0; ll.y = l1;
      unsigned off = (unsigned)((d + j)*W_STR + o)*2;
      *(__half2*)(smem + W_BHI + off) = hh;
      *(__half2*)(smem + W_BLO + off) = ll;
    }
  }
  __syncthreads();

  float acc[2][4][4];
  #pragma unroll
  for (int i = 0; i < 2; i++)
    #pragma unroll
    for (int j = 0; j < 4; j++)
      #pragma unroll
      for (int q = 0; q < 4; q++) acc[i][j][q] = 0.f;

  #pragma unroll
  for (int ks = 0; ks < 16; ks++){
    const int k = ks*16;
    unsigned ah[2][4], al[2][4], bh[2][4], bl[2][4];
    #pragma unroll
    for (int mi = 0; mi < 2; mi++){
      unsigned aoff =
        (unsigned)((wm*32 + mi*16 + (lane & 15))*W_STR + k + ((lane >> 4) << 3))*2;
      ldsm4(ah[mi], sbase + W_AHI + aoff);
      ldsm4(al[mi], sbase + W_ALO + aoff);
    }
    #pragma unroll
    for (int ng = 0; ng < 2; ng++){
      unsigned boff =
        (unsigned)((wn*32 + ng*16 + (lane & 7) + ((lane >> 4) << 3))*W_STR + k + (((lane >> 3) & 1) << 3))*2;
      ldsm4(bh[ng], sbase + W_BHI + boff);
      ldsm4(bl[ng], sbase + W_BLO + boff);
    }
    #pragma unroll
    for (int mi = 0; mi < 2; mi++)
      #pragma unroll
      for (int ng = 0; ng < 2; ng++){
        mma16816(acc[mi][2*ng+0], ah[mi], &bh[ng][0]);
        mma16816(acc[mi][2*ng+1], ah[mi], &bh[ng][2]);
        mma16816(acc[mi][2*ng+0], ah[mi], &bl[ng][0]);
        mma16816(acc[mi][2*ng+1], ah[mi], &bl[ng][2]);
        mma16816(acc[mi][2*ng+0], al[mi], &bh[ng][0]);
        mma16816(acc[mi][2*ng+1], al[mi], &bh[ng][2]);
      }
  }

  // epilogue: g_wt[row=n][col=r*64+d], fp16
  #pragma unroll
  for (int mi = 0; mi < 2; mi++){
    int row = n0 + wm*32 + mi*16 + (lane >> 2);
    #pragma unroll
    for (int nj = 0; nj < 4; nj++){
      int col = r*64 + wn*32 + nj*8 + (lane & 3)*2;
      __half2 v01 = __floats2half2_rn(acc[mi][nj][0], acc[mi][nj][1]);
      __half2 v23 = __floats2half2_rn(acc[mi][nj][2], acc[mi][nj][3]);
      *(__half2*)(g_wt + (size_t)row*KAUG + col) = v01;
      *(__half2*)(g_wt + (size_t)(row + 8)*KAUG + col) = v23;
    }
  }
}

// ================= main mma.sync GEMM (single fp16 product) =================
#define ATILE 18432
#define BOFF  36864
#define HOFF  73728
#define SMTOT 107008
#define SSTR  72

__global__ void __launch_bounds__(256, 1) k_gemm(const int* __restrict__ nidx){
  extern __shared__ __align__(16) char smem[];
  const unsigned sbase = (unsigned)__cvta_generic_to_shared(smem);
  float* sHdd = (float*)(smem + HOFF);

  const int tid  = threadIdx.x;
  const int lane = tid & 31;
  const int wid  = tid >> 5;
  const int wm   = wid & 3;
  const int wn   = wid >> 2;
  const int m0   = blockIdx.x * 128;
  const int n0   = blockIdx.y * 128;

  #pragma unroll
  for (int i = 0; i < 32; i++){
    int idx = tid + i*256;
    int row = idx >> 6, c = idx & 63;
    sHdd[row*65 + c] = g_hdd[(size_t)(m0+row)*64 + c];
  }
  const int arow  = tid >> 1;
  const int halfc = (tid & 1) * 32;
  float xev[32];
  {
    int e    = m0 + arow;
    int node = e >> 4;
    int b    = node >> 8;
    int nb   = b*NN + nidx[e];
    const float* pj = g_xj + (size_t)nb*ND + halfc;
    const float* pi = g_xi + (size_t)node*ND + halfc;
    #pragma unroll
    for (int j = 0; j < 32; j++) xev[j] = pj[j] + pi[j];
  }
  __syncthreads();

  const __half* wB = g_wt + (size_t)n0*KAUG;

  auto loadB = [&](int s, int kbase){
    unsigned sm0 = sbase + BOFF + (unsigned)s*ATILE;
    #pragma unroll
    for (int i = 0; i < 4; i++){
      int q = tid + i*256;
      int row = q >> 3, w8 = q & 7;
      cpasync16(sm0 + (unsigned)(row*SSTR + w8*8)*2,
                wB + (size_t)row*KAUG + kbase + w8*8);
    }
  };
  auto buildA = [&](int s, int r){
    float h = (r < 64) ? sHdd[arow*65 + r] : 1.0f;
    char* aT = smem + s*ATILE;
    unsigned off = (unsigned)(arow*SSTR + halfc)*2;
    #pragma unroll
    for (int c = 0; c < 4; c++){
      uint4 hv;
      unsigned* hp = (unsigned*)&hv;
      #pragma unroll
      for (int m = 0; m < 4; m++){
        __half2 hh = __floats2half2_rn(h * xev[c*8 + 2*m], h * xev[c*8 + 2*m + 1]);
        hp[m] = *(unsigned*)&hh;
      }
      *(uint4*)(aT + off + c*16) = hv;
    }
  };

  float acc[2][8][4];
  #pragma unroll
  for (int i = 0; i < 2; i++)
    #pragma unroll
    for (int j = 0; j < 8; j++)
      #pragma unroll
      for (int q = 0; q < 4; q++) acc[i][j][q] = 0.f;

  loadB(0, 0);
  asm volatile("cp.async.commit_group;" ::: "memory");
  buildA(0, 0);

  for (int r = 0; r <= 64; r++){
    const int s = r & 1;
    if (r < 64){
      int kb = (r + 1 < 64) ? (r + 1)*64 : 4096;
      loadB(s ^ 1, kb);
      asm volatile("cp.async.commit_group;" ::: "memory");
      buildA(s ^ 1, r + 1);
      asm volatile("cp.async.wait_group 1;" ::: "memory");
    } else {
      asm volatile("cp.async.wait_group 0;" ::: "memory");
    }
    __syncthreads();

    const unsigned aB = sbase + (unsigned)s*ATILE;
    const unsigned bB = sbase + BOFF + (unsigned)s*ATILE;
    #pragma unroll
    for (int ks = 0; ks < 4; ks++){
      const int kk = ks*16;
      unsigned a[2][4], b[4][4];
      #pragma unroll
      for (int mi = 0; mi < 2; mi++){
        unsigned aoff =
          (unsigned)((wm*32 + mi*16 + (lane & 15))*SSTR + kk + ((lane >> 4) << 3))*2;
        ldsm4(a[mi], aB + aoff);
      }
      #pragma unroll
      for (int ng = 0; ng < 4; ng++){
        int nb = wn*64 + ng*16;
        unsigned addr = bB +
          (unsigned)((nb + (lane & 7) + ((lane >> 4) << 3))*SSTR + kk + (((lane >> 3) & 1) << 3))*2;
        ldsm4(b[ng], addr);
      }
      #pragma unroll
      for (int mi = 0; mi < 2; mi++)
        #pragma unroll
        for (int ng = 0; ng < 4; ng++){
          mma16816(acc[mi][2*ng+0], a[mi], &b[ng][0]);
          mma16816(acc[mi][2*ng+1], a[mi], &b[ng][2]);
        }
    }
    __syncthreads();
  }

  #pragma unroll
  for (int mi = 0; mi < 2; mi++){
    int row = m0 + wm*32 + mi*16 + (lane >> 2);
    #pragma unroll
    for (int nj = 0; nj < 8; nj++){
      int col = n0 + wn*64 + nj*8 + (lane & 3)*2;
      float* d = g_kv + (size_t)row*NKVD + col;
      *(float2*)d = make_float2(acc[mi][nj][0], acc[mi][nj][1]);
      *(float2*)(d + 8*NKVD) = make_float2(acc[mi][nj][2], acc[mi][nj][3]);
    }
  }
}

// ---------------- attention + out projection ----------------
__global__ void k_attn(const float* __restrict__ Wout, float* __restrict__ out){
  __shared__ float s_out[NHID];
  int node = blockIdx.x;
  int tid  = threadIdx.x;
  float qv = g_q[node*NHID + tid];

  float sim[NK];
  #pragma unroll
  for (int j = 0; j < NK; j++){
    int e = node*NK + j;
    float kvv = g_kv[(size_t)e*NKVD + tid];
    float dff = qv - kvv + 1e-6f;
    float s = dff * dff;
    #pragma unroll
    for (int o = 16; o; o >>= 1) s += __shfl_xor_sync(0xffffffffu, s, o);
    float m = g_maskf[e];
    sim[j] = (m != 0.f) ? (-sqrtf(s) * 0.17677669529663687f) : -3.402823466e38f;
  }
  float mx = sim[0];
  #pragma unroll
  for (int j = 1; j < NK; j++) mx = fmaxf(mx, sim[j]);
  float p[NK], den = 0.f;
  #pragma unroll
  for (int j = 0; j < NK; j++){ p[j] = expf(sim[j] - mx); den += p[j]; }
  float o = 0.f;
  #pragma unroll
  for (int j = 0; j < NK; j++){
    int e = node*NK + j;
    o = fmaf(p[j], g_kv[(size_t)e*NKVD + NHID + tid], o);
  }
  s_out[tid] = o / den;
  __syncthreads();
  if (tid < ND){
    float a = 0.f;
    #pragma unroll
    for (int c = 0; c < NHID; c++) a = fmaf(s_out[c], Wout[c*ND + tid], a);
    out[node*ND + tid] = a;
  }
}

// ---------------- launch ----------------
extern "C" void kernel_launch(void* const* d_in, const int* in_sizes, int n_in,
                              void* d_out, int out_size){
  const float* features = (const float*)d_in[0];
  const int*   nidx     = (const int*)  d_in[1];
  const unsigned char* mask = (const unsigned char*)d_in[2];
  const float* rel      = (const float*)d_in[3];
  const float* nscale   = (const float*)d_in[4];
  const float* Wq       = (const float*)d_in[5];
  const float* Wxi      = (const float*)d_in[6];
  const float* Wxj      = (const float*)d_in[7];
  const float* rp_W1    = (const float*)d_in[8];
  const float* rp_b1    = (const float*)d_in[9];
  const float* rp_g1    = (const float*)d_in[10];
  const float* rp_W2    = (const float*)d_in[11];
  const float* rp_b2    = (const float*)d_in[12];
  const float* rp_g2    = (const float*)d_in[13];
  const float* rp_W3    = (const float*)d_in[14];
  const float* rp_b3    = (const float*)d_in[15];
  const float* Wkv      = (const float*)d_in[16];
  const float* Wout     = (const float*)d_in[17];
  float* out = (float*)d_out;

  cudaFuncSetAttribute(k_wcomb, cudaFuncAttributeMaxDynamicSharedMemorySize, W_SMT);
  cudaFuncSetAttribute(k_gemm,  cudaFuncAttributeMaxDynamicSharedMemorySize, SMTOT);

  k_pre    <<<NODES + 1, 256>>>(features, nscale, Wq, Wxi, Wxj, mask);
  k_radial <<<1024, 256>>>(rel, rp_W1, rp_b1, rp_g1, rp_W2, rp_b2, rp_g2);
  k_wcomb  <<<dim3(65, 2), 256, W_SMT>>>(rp_W3, rp_b3, Wkv);
  k_gemm   <<<dim3(64, 2), 256, SMTOT>>>(nidx);
  k_attn   <<<NODES, 128>>>(Wout, out);
}